// round 12
// baseline (speedup 1.0000x reference)
#include <cuda_runtime.h>
#include <math.h>
#include <stdint.h>

// ---------------------------------------------------------------------------
// Problem constants (MonArcHeadLayer): B=2, S=1024, HIDDEN=2048, 32 heads x 64,
// ROT_DIM=16, D_FF=8192, fp32 end-to-end. GEMMs on tf32 tensor cores.
// ---------------------------------------------------------------------------
#define HIDDEN  2048
#define NHEADS  32
#define HDIM    64
#define ROT     16
#define DFF     8192
#define SQ      1024
#define BATCH   2
#define NTOK    (BATCH * SQ)     // 2048 tokens
#define EPS     1e-5f

// ---------------------------------------------------------------------------
// Static scratch (no allocation allowed in kernel_launch)
// ---------------------------------------------------------------------------
__device__ float g_xln [NTOK * HIDDEN];   // LN1 output
__device__ float g_q   [NTOK * HIDDEN];   // Q proj (layout [t, h*64+d])
__device__ float g_k   [NTOK * HIDDEN];
__device__ float g_v   [NTOK * HIDDEN];
__device__ float g_ctx [NTOK * HIDDEN];   // attention context
__device__ float g_h   [NTOK * HIDDEN];   // residual + attn_out
__device__ float g_yln [NTOK * HIDDEN];   // LN2 output
__device__ float g_gate[NTOK * DFF];      // gate proj -> reused for activation
__device__ float g_up  [NTOK * DFF];      // up proj

// ---------------------------------------------------------------------------
// LayerNorm: one block per token, 256 threads
// ---------------------------------------------------------------------------
__global__ __launch_bounds__(256) void ln_kernel(
    const float* __restrict__ x, const float* __restrict__ w,
    const float* __restrict__ b, float* __restrict__ out)
{
    int t = blockIdx.x;
    const float* xr = x + (size_t)t * HIDDEN;
    float* orow = out + (size_t)t * HIDDEN;

    float s = 0.f, ss = 0.f;
    for (int i = threadIdx.x; i < HIDDEN; i += 256) {
        float v = xr[i];
        s += v; ss += v * v;
    }
    __shared__ float red_s[8], red_ss[8];
    #pragma unroll
    for (int o = 16; o; o >>= 1) {
        s  += __shfl_xor_sync(0xffffffffu, s,  o);
        ss += __shfl_xor_sync(0xffffffffu, ss, o);
    }
    int wid = threadIdx.x >> 5, lid = threadIdx.x & 31;
    if (lid == 0) { red_s[wid] = s; red_ss[wid] = ss; }
    __syncthreads();
    if (wid == 0) {
        s  = (lid < 8) ? red_s[lid]  : 0.f;
        ss = (lid < 8) ? red_ss[lid] : 0.f;
        #pragma unroll
        for (int o = 4; o; o >>= 1) {
            s  += __shfl_xor_sync(0xffffffffu, s,  o);
            ss += __shfl_xor_sync(0xffffffffu, ss, o);
        }
        if (lid == 0) { red_s[0] = s * (1.f / HIDDEN); red_ss[0] = ss * (1.f / HIDDEN); }
    }
    __syncthreads();
    float mu  = red_s[0];
    float var = red_ss[0] - mu * mu;
    float inv = rsqrtf(var + EPS);
    for (int i = threadIdx.x; i < HIDDEN; i += 256)
        orow[i] = (xr[i] - mu) * inv * w[i] + b[i];
}

// ---------------------------------------------------------------------------
// tf32 helpers
// ---------------------------------------------------------------------------
__device__ __forceinline__ float tf32r(float x) {
    uint32_t u;
    asm("cvt.rn.tf32.f32 %0, %1;" : "=r"(u) : "f"(x));
    return __uint_as_float(u);
}

__device__ __forceinline__ void mma_tf32(
    float4& c, uint32_t a0, uint32_t a1, uint32_t a2, uint32_t a3,
    uint32_t b0, uint32_t b1)
{
    asm volatile(
        "mma.sync.aligned.m16n8k8.row.col.f32.tf32.tf32.f32 "
        "{%0,%1,%2,%3}, {%4,%5,%6,%7}, {%8,%9}, {%0,%1,%2,%3};\n"
        : "+f"(c.x), "+f"(c.y), "+f"(c.z), "+f"(c.w)
        : "r"(a0), "r"(a1), "r"(a2), "r"(a3), "r"(b0), "r"(b1));
}

// ---------------------------------------------------------------------------
// Tensor-core GEMM (NT): C[M,N] = A[M,K] * B[N,K]^T  (+ optional add)
// A row-major [M,K], B row-major [N,K] (== col-major k x n operand).
// 128x128 CTA tile, 256 threads, 8 warps as 2(m) x 4(n), warp tile 64x32,
// BK=16, m16n8k8 tf32 MMA.
//
// Smem layout: per row of 16 k-values, PERMUTED as pos(c) = (c&3)*4 + (c>>2),
// row stride SKA=20 floats. A lane's 4 k-values for both k-steps
// {tg, tg+4, tg+8, tg+12} are then contiguous -> one LDS.128 per fragment row
// (12 LDS.128 per thread per k-tile vs 48 LDS.32 before). Stride 20 makes both
// the LDS.128 reads (row starts evenly spaced mod 32 banks -> 4 wavefronts,
// the floor) and the scattered STS.32 commits conflict-free.
// Double-buffered smem: one __syncthreads per k-tile; MMA overlaps STS+LDG.
// All dims are multiples of 128/16 here, no edge guards.
// ---------------------------------------------------------------------------
#define TBM 128
#define TBN 128
#define TBK 16
#define SKA 20

__global__ __launch_bounds__(256, 2) void tgemm_nt(
    const float* __restrict__ A, const float* __restrict__ B,
    float* __restrict__ C, const float* __restrict__ add,
    int M, int N, int K)
{
    __shared__ __align__(16) float As[2][TBM * SKA];
    __shared__ __align__(16) float Bs[2][TBN * SKA];

    int tid  = threadIdx.x;
    int warp = tid >> 5, lane = tid & 31;
    int g  = lane >> 2;        // 0..7
    int tg = lane & 3;         // 0..3
    int wm = (warp & 1) * 64;  // warp m-offset
    int wn = (warp >> 1) * 32; // warp n-offset
    int m0 = blockIdx.y * TBM;
    int n0 = blockIdx.x * TBN;

    float4 acc[4][4];
    #pragma unroll
    for (int i = 0; i < 4; i++)
        #pragma unroll
        for (int j = 0; j < 4; j++)
            acc[i][j] = make_float4(0.f, 0.f, 0.f, 0.f);

    // global load mapping: rows tid/4 and tid/4+64, cols (tid%4)*4
    int lrow = tid >> 2;
    int c4   = tid & 3;             // k-group: cols c4*4 .. c4*4+3
    const float* Ap = A + (size_t)(m0 + lrow) * K + c4 * 4;
    const float* Bp = B + (size_t)(n0 + lrow) * K + c4 * 4;

    // permuted store positions for this thread's 4 columns:
    // col c4*4+j -> pos j*4 + c4
    int sA0 = lrow * SKA + c4;           // + j*4
    int sA1 = (lrow + 64) * SKA + c4;

    float4 pa0 = *(const float4*)(Ap);
    float4 pa1 = *(const float4*)(Ap + (size_t)64 * K);
    float4 pb0 = *(const float4*)(Bp);
    float4 pb1 = *(const float4*)(Bp + (size_t)64 * K);

    // commit tile 0 into stage 0
    {
        float* as = As[0]; float* bs = Bs[0];
        as[sA0 + 0] = tf32r(pa0.x); as[sA0 + 4] = tf32r(pa0.y);
        as[sA0 + 8] = tf32r(pa0.z); as[sA0 +12] = tf32r(pa0.w);
        as[sA1 + 0] = tf32r(pa1.x); as[sA1 + 4] = tf32r(pa1.y);
        as[sA1 + 8] = tf32r(pa1.z); as[sA1 +12] = tf32r(pa1.w);
        bs[sA0 + 0] = tf32r(pb0.x); bs[sA0 + 4] = tf32r(pb0.y);
        bs[sA0 + 8] = tf32r(pb0.z); bs[sA0 +12] = tf32r(pb0.w);
        bs[sA1 + 0] = tf32r(pb1.x); bs[sA1 + 4] = tf32r(pb1.y);
        bs[sA1 + 8] = tf32r(pb1.z); bs[sA1 +12] = tf32r(pb1.w);
    }
    __syncthreads();

    int s = 0;
    for (int k0 = 0; k0 < K; k0 += TBK) {
        int kn = k0 + TBK;
        bool more = kn < K;
        if (more) {
            pa0 = *(const float4*)(Ap + kn);
            pa1 = *(const float4*)(Ap + (size_t)64 * K + kn);
            pb0 = *(const float4*)(Bp + kn);
            pb1 = *(const float4*)(Bp + (size_t)64 * K + kn);
        }

        // B fragments: one LDS.128 per nt covers both k-steps
        const float* as = As[s]; const float* bs = Bs[s];
        float4 bf[4];
        #pragma unroll
        for (int nt = 0; nt < 4; nt++)
            bf[nt] = *(const float4*)&bs[(wn + nt * 8 + g) * SKA + tg * 4];

        #pragma unroll
        for (int mt = 0; mt < 4; mt++) {
            int r = (wm + mt * 16 + g) * SKA + tg * 4;
            float4 alo = *(const float4*)&as[r];
            float4 ahi = *(const float4*)&as[r + 8 * SKA];
            // k-step 0: cols {tg, tg+4} = (.x, .y)
            #pragma unroll
            for (int nt = 0; nt < 4; nt++)
                mma_tf32(acc[mt][nt],
                         __float_as_uint(alo.x), __float_as_uint(ahi.x),
                         __float_as_uint(alo.y), __float_as_uint(ahi.y),
                         __float_as_uint(bf[nt].x), __float_as_uint(bf[nt].y));
            // k-step 1: cols {tg+8, tg+12} = (.z, .w)
            #pragma unroll
            for (int nt = 0; nt < 4; nt++)
                mma_tf32(acc[mt][nt],
                         __float_as_uint(alo.z), __float_as_uint(ahi.z),
                         __float_as_uint(alo.w), __float_as_uint(ahi.w),
                         __float_as_uint(bf[nt].z), __float_as_uint(bf[nt].w));
        }

        if (more) {
            float* aw = As[s ^ 1]; float* bw = Bs[s ^ 1];
            aw[sA0 + 0] = tf32r(pa0.x); aw[sA0 + 4] = tf32r(pa0.y);
            aw[sA0 + 8] = tf32r(pa0.z); aw[sA0 +12] = tf32r(pa0.w);
            aw[sA1 + 0] = tf32r(pa1.x); aw[sA1 + 4] = tf32r(pa1.y);
            aw[sA1 + 8] = tf32r(pa1.z); aw[sA1 +12] = tf32r(pa1.w);
            bw[sA0 + 0] = tf32r(pb0.x); bw[sA0 + 4] = tf32r(pb0.y);
            bw[sA0 + 8] = tf32r(pb0.z); bw[sA0 +12] = tf32r(pb0.w);
            bw[sA1 + 0] = tf32r(pb1.x); bw[sA1 + 4] = tf32r(pb1.y);
            bw[sA1 + 8] = tf32r(pb1.z); bw[sA1 +12] = tf32r(pb1.w);
            __syncthreads();
        }
        s ^= 1;
    }

    // epilogue: c0/c1 -> row g, cols 2tg,2tg+1 ; c2/c3 -> row g+8
    #pragma unroll
    for (int mt = 0; mt < 4; mt++) {
        int m = m0 + wm + mt * 16 + g;
        #pragma unroll
        for (int nt = 0; nt < 4; nt++) {
            int n = n0 + wn + nt * 8 + 2 * tg;
            float2 r0 = make_float2(acc[mt][nt].x, acc[mt][nt].y);
            float2 r1 = make_float2(acc[mt][nt].z, acc[mt][nt].w);
            if (add) {
                float2 a0 = *(const float2*)(add + (size_t)m * N + n);
                float2 a1 = *(const float2*)(add + (size_t)(m + 8) * N + n);
                r0.x += a0.x; r0.y += a0.y;
                r1.x += a1.x; r1.y += a1.y;
            }
            *(float2*)(C + (size_t)m * N + n)       = r0;
            *(float2*)(C + (size_t)(m + 8) * N + n) = r1;
        }
    }
}

// ---------------------------------------------------------------------------
// RoPE in-place on first ROT dims of every head. One thread per (token, head).
// ---------------------------------------------------------------------------
__global__ void rope_kernel(float* __restrict__ qk, const int* __restrict__ pos_ids)
{
    int idx = blockIdx.x * blockDim.x + threadIdx.x;
    if (idx >= NTOK * NHEADS) return;
    int t = idx / NHEADS, h = idx % NHEADS;
    float pos = (float)pos_ids[t];
    float* p = qk + (size_t)t * HIDDEN + h * HDIM;

    float x[ROT];
    #pragma unroll
    for (int j = 0; j < ROT; j++) x[j] = p[j];

    #pragma unroll
    for (int i = 0; i < ROT / 2; i++) {
        float invf = powf(10000.f, -(float)i / (ROT / 2));
        float f = pos * invf;
        float c = cosf(f), s = sinf(f);
        float lo = x[i], hi = x[i + ROT / 2];
        p[i]           = lo * c - hi * s;
        p[i + ROT / 2] = hi * c + lo * s;
    }
}

// ---------------------------------------------------------------------------
// Flash attention fp32. One block = (128 q-rows, one head, one batch).
// One thread owns one q-row: q[64] and o[64] in registers, online softmax.
// ---------------------------------------------------------------------------
#define BQ  128
#define BKT 32

__global__ __launch_bounds__(128) void attn_kernel(const float* __restrict__ mask)
{
    __shared__ __align__(16) float Ks[BKT][HDIM];
    __shared__ __align__(16) float Vs[BKT][HDIM];
    __shared__ float Ms[BQ][BKT + 1];

    int b  = blockIdx.z;
    int h  = blockIdx.y;
    int q0 = blockIdx.x * BQ;
    int tid = threadIdx.x;
    int qi = q0 + tid;
    int t  = b * SQ + qi;

    const float* qrow  = g_q + (size_t)t * HIDDEN + h * HDIM;
    const float* kbase = g_k + (size_t)(b * SQ) * HIDDEN + h * HDIM;
    const float* vbase = g_v + (size_t)(b * SQ) * HIDDEN + h * HDIM;

    float4 qv[16], ov[16];
    #pragma unroll
    for (int i = 0; i < 16; i++) {
        qv[i] = *(const float4*)(qrow + i * 4);
        ov[i] = make_float4(0.f, 0.f, 0.f, 0.f);
    }
    float m = -1e30f, l = 0.f;
    const float scale = 0.125f;

    for (int k0 = 0; k0 < SQ; k0 += BKT) {
        for (int i = tid * 4; i < BKT * HDIM; i += 128 * 4) {
            int r = i >> 6, c = i & 63;
            *(float4*)&Ks[r][c] = *(const float4*)(kbase + (size_t)(k0 + r) * HIDDEN + c);
            *(float4*)&Vs[r][c] = *(const float4*)(vbase + (size_t)(k0 + r) * HIDDEN + c);
        }
        for (int i = tid * 4; i < BQ * BKT; i += 128 * 4) {
            int r = i >> 5, c = i & 31;
            float4 mv = *(const float4*)(mask + ((size_t)(b * SQ + q0 + r)) * SQ + k0 + c);
            Ms[r][c + 0] = mv.x; Ms[r][c + 1] = mv.y;
            Ms[r][c + 2] = mv.z; Ms[r][c + 3] = mv.w;
        }
        __syncthreads();

        float sc[BKT];
        float tmax = m;
        #pragma unroll
        for (int kj = 0; kj < BKT; kj++) {
            float s = 0.f;
            #pragma unroll
            for (int d4 = 0; d4 < 16; d4++) {
                float4 kv = *(const float4*)&Ks[kj][d4 * 4];
                s = fmaf(qv[d4].x, kv.x, s);
                s = fmaf(qv[d4].y, kv.y, s);
                s = fmaf(qv[d4].z, kv.z, s);
                s = fmaf(qv[d4].w, kv.w, s);
            }
            s = s * scale + Ms[tid][kj];
            sc[kj] = s;
            tmax = fmaxf(tmax, s);
        }
        float corr = expf(m - tmax);
        m = tmax;
        l *= corr;
        #pragma unroll
        for (int i = 0; i < 16; i++) {
            ov[i].x *= corr; ov[i].y *= corr; ov[i].z *= corr; ov[i].w *= corr;
        }
        #pragma unroll
        for (int kj = 0; kj < BKT; kj++) {
            float e = expf(sc[kj] - m);
            l += e;
            #pragma unroll
            for (int d4 = 0; d4 < 16; d4++) {
                float4 vv = *(const float4*)&Vs[kj][d4 * 4];
                ov[d4].x = fmaf(e, vv.x, ov[d4].x);
                ov[d4].y = fmaf(e, vv.y, ov[d4].y);
                ov[d4].z = fmaf(e, vv.z, ov[d4].z);
                ov[d4].w = fmaf(e, vv.w, ov[d4].w);
            }
        }
        __syncthreads();
    }

    float inv = 1.f / l;
    float* orow = g_ctx + (size_t)t * HIDDEN + h * HDIM;
    #pragma unroll
    for (int i = 0; i < 16; i++) {
        float4 r = make_float4(ov[i].x * inv, ov[i].y * inv, ov[i].z * inv, ov[i].w * inv);
        *(float4*)(orow + i * 4) = r;
    }
}

// ---------------------------------------------------------------------------
// SwiGLU activation: g = silu(g) * u, elementwise, vectorized
// ---------------------------------------------------------------------------
__global__ void silu_mul_kernel(float* __restrict__ g, const float* __restrict__ u, int n4)
{
    int i = blockIdx.x * blockDim.x + threadIdx.x;
    if (i >= n4) return;
    float4 gv = ((const float4*)g)[i];
    float4 uv = ((const float4*)u)[i];
    gv.x = gv.x / (1.f + expf(-gv.x)) * uv.x;
    gv.y = gv.y / (1.f + expf(-gv.y)) * uv.y;
    gv.z = gv.z / (1.f + expf(-gv.z)) * uv.z;
    gv.w = gv.w / (1.f + expf(-gv.w)) * uv.w;
    ((float4*)g)[i] = gv;
}

// ---------------------------------------------------------------------------
// Launch
// Inputs (metadata order): hidden_states, memory, attention_mask, position_ids,
// Wq, Wk, Wv, Wo, ln1_w, ln1_b, ln2_w, ln2_b, gate_w, up_w, down_w
// ---------------------------------------------------------------------------
extern "C" void kernel_launch(void* const* d_in, const int* in_sizes, int n_in,
                              void* d_out, int out_size)
{
    const float* hs    = (const float*)d_in[0];
    const float* mem   = (const float*)d_in[1];
    const float* mask  = (const float*)d_in[2];
    const int*   pos   = (const int*)  d_in[3];
    const float* Wq    = (const float*)d_in[4];
    const float* Wk    = (const float*)d_in[5];
    const float* Wv    = (const float*)d_in[6];
    const float* Wo    = (const float*)d_in[7];
    const float* ln1w  = (const float*)d_in[8];
    const float* ln1b  = (const float*)d_in[9];
    const float* ln2w  = (const float*)d_in[10];
    const float* ln2b  = (const float*)d_in[11];
    const float* gatew = (const float*)d_in[12];
    const float* upw   = (const float*)d_in[13];
    const float* downw = (const float*)d_in[14];
    float* out = (float*)d_out;

    float *xln, *q, *k, *v, *ctx, *h, *yln, *gate, *up;
    cudaGetSymbolAddress((void**)&xln,  g_xln);
    cudaGetSymbolAddress((void**)&q,    g_q);
    cudaGetSymbolAddress((void**)&k,    g_k);
    cudaGetSymbolAddress((void**)&v,    g_v);
    cudaGetSymbolAddress((void**)&ctx,  g_ctx);
    cudaGetSymbolAddress((void**)&h,    g_h);
    cudaGetSymbolAddress((void**)&yln,  g_yln);
    cudaGetSymbolAddress((void**)&gate, g_gate);
    cudaGetSymbolAddress((void**)&up,   g_up);

    // 1. LN1
    ln_kernel<<<NTOK, 256>>>(hs, ln1w, ln1b, xln);

    // 2. Q/K/V projections (NT gemm: x @ W^T) — tf32 tensor cores
    dim3 g2048(HIDDEN / TBN, NTOK / TBM);
    tgemm_nt<<<g2048, 256>>>(xln, Wq, q, nullptr, NTOK, HIDDEN, HIDDEN);
    tgemm_nt<<<g2048, 256>>>(mem, Wk, k, nullptr, NTOK, HIDDEN, HIDDEN);
    tgemm_nt<<<g2048, 256>>>(mem, Wv, v, nullptr, NTOK, HIDDEN, HIDDEN);

    // 3. RoPE on q and k
    int nrope = NTOK * NHEADS;
    rope_kernel<<<(nrope + 255) / 256, 256>>>(q, pos);
    rope_kernel<<<(nrope + 255) / 256, 256>>>(k, pos);

    // 4. Attention
    attn_kernel<<<dim3(SQ / BQ, NHEADS, BATCH), 128>>>(mask);

    // 5. O projection + residual  (h = hs + ctx @ Wo^T)
    tgemm_nt<<<g2048, 256>>>(ctx, Wo, h, hs, NTOK, HIDDEN, HIDDEN);

    // 6. LN2
    ln_kernel<<<NTOK, 256>>>(h, ln2w, ln2b, yln);

    // 7. MLP gate/up
    dim3 g8192(DFF / TBN, NTOK / TBM);
    tgemm_nt<<<g8192, 256>>>(yln, gatew, gate, nullptr, NTOK, DFF, HIDDEN);
    tgemm_nt<<<g8192, 256>>>(yln, upw,   up,   nullptr, NTOK, DFF, HIDDEN);

    // 8. silu(gate) * up  -> gate (in place)
    int n4 = NTOK * DFF / 4;
    silu_mul_kernel<<<(n4 + 255) / 256, 256>>>(gate, up, n4);

    // 9. down projection + residual -> out
    tgemm_nt<<<g2048, 256>>>(gate, downw, out, h, NTOK, HIDDEN, DFF);

    (void)in_sizes; (void)n_in; (void)out_size;
}